// round 7
// baseline (speedup 1.0000x reference)
#include <cuda_runtime.h>
#include <math.h>
#include <cstdint>

// ---------------- problem constants ----------------
#define BN_ 16384
#define D_IN 1024
#define H1 512
#define H2 256
#define H3 128
#define FH 64
#define NDOM 4
#define EMB 16
#define BMROWS 128
#define BP 16896            // 132 tiles of 128 (>= 16384 + max padding 508)
#define NCB 64              // count blocks

// ---------------- scratch (device globals) ----------------
__device__ float g_norm[(size_t)BP * D_IN];
__device__ float g_h1c[(size_t)BP * H1];
__device__ float g_h1d[(size_t)BP * H1];
__device__ float g_h2c[(size_t)BP * H2];
__device__ float g_h2d[(size_t)BP * H2];
__device__ float g_h3c[(size_t)BP * H3];
__device__ float g_h3d[(size_t)BP * H3];
__device__ int   g_perm[BP];
__device__ int   g_bcnt[NCB][NDOM];
__device__ int   g_cnt[NDOM];
__device__ int   g_off[NDOM];
__device__ float g_aux[NDOM];

typedef unsigned long long u64;

// ---------------- f32x2 helpers ----------------
__device__ __forceinline__ void fma2(u64& d, u64 a, u64 b) {
    asm("fma.rn.f32x2 %0, %1, %2, %0;" : "+l"(d) : "l"(a), "l"(b));
}
__device__ __forceinline__ float2 unpack2(u64 v) {
    uint32_t lo, hi;
    asm("mov.b64 {%0, %1}, %2;" : "=r"(lo), "=r"(hi) : "l"(v));
    float2 f;
    f.x = __uint_as_float(lo);
    f.y = __uint_as_float(hi);
    return f;
}

__device__ __forceinline__ uint32_t smem_u32(const void* p) {
    uint32_t a;
    asm("{ .reg .u64 t; cvta.to.shared.u64 t, %1; cvt.u32.u64 %0, t; }" : "=r"(a) : "l"(p));
    return a;
}
__device__ __forceinline__ void cp_async16(uint32_t dst, const void* src) {
    asm volatile("cp.async.ca.shared.global [%0], [%1], 16;"
                 :: "r"(dst), "l"(src) : "memory");
}
__device__ __forceinline__ void cp_commit() {
    asm volatile("cp.async.commit_group;" ::: "memory");
}
template <int N>
__device__ __forceinline__ void cp_wait() {
    asm volatile("cp.async.wait_group %0;" :: "n"(N) : "memory");
}

// pad region helpers
__device__ __forceinline__ int pad4(int c) { return (c + BMROWS - 1) & ~(BMROWS - 1); }

__device__ __forceinline__ int dom_of(int p) {
    int d = 0;
    #pragma unroll
    for (int k = 1; k < NDOM; k++) d += (p >= g_off[k]);
    return d;
}

// ---------------- sort: count (per-block partials) ----------------
__global__ __launch_bounds__(256) void count_kernel(const int* __restrict__ dids) {
    __shared__ int sc[NDOM];
    int tid = threadIdx.x;
    if (tid < NDOM) sc[tid] = 0;
    __syncthreads();
    int i = blockIdx.x * 256 + tid;
    atomicAdd(&sc[dids[i]], 1);
    __syncthreads();
    if (tid < NDOM) g_bcnt[blockIdx.x][tid] = sc[tid];
}

// ---------------- sort: scatter with inline prefix (publishes off/cnt) ----------------
__global__ __launch_bounds__(256) void scatter_kernel(const int* __restrict__ dids) {
    __shared__ int pre[NDOM];
    __shared__ int loc[NDOM];
    __shared__ int stot[NDOM], sbase[NDOM];
    int tid = threadIdx.x;
    if (tid < NDOM) {
        int d = tid, base = 0, tot = 0;
        #pragma unroll 8
        for (int b = 0; b < NCB; b++) {
            int c = g_bcnt[b][d];
            if (b < (int)blockIdx.x) base += c;
            tot += c;
        }
        stot[d] = tot; sbase[d] = base;
        loc[d] = 0;
    }
    __syncthreads();
    if (tid == 0) {
        int off = 0;
        #pragma unroll
        for (int d = 0; d < NDOM; d++) {
            pre[d] = off + sbase[d];
            if (blockIdx.x == 0) { g_off[d] = off; g_cnt[d] = stot[d]; }
            off += pad4(stot[d]);
        }
    }
    __syncthreads();
    int i = blockIdx.x * 256 + tid;
    int d = dids[i];
    int rank = atomicAdd(&loc[d], 1);
    g_perm[pre[d] + rank] = i;
}

// aux net (domain-only) -> 4 scalars
__global__ void aux_kernel(const float* __restrict__ dom_emb,
                           const float* __restrict__ aW1, const float* __restrict__ ab1,
                           const float* __restrict__ aW2, const float* __restrict__ ab2) {
    int w = threadIdx.x >> 5;
    int j = threadIdx.x & 31;
    float s = ab1[j];
    #pragma unroll
    for (int i = 0; i < EMB; i++) s += dom_emb[w * EMB + i] * aW1[i * 32 + j];
    float v = fmaxf(s, 0.f) * aW2[j];
    #pragma unroll
    for (int o = 16; o; o >>= 1) v += __shfl_xor_sync(0xFFFFFFFFu, v, o);
    if (j == 0) g_aux[w] = v + ab2[0];
}

// ---------------- layernorm + domain affine, permuted order ----------------
__global__ __launch_bounds__(256) void ln_kernel(const float* __restrict__ x,
                                                 const int* __restrict__ dids,
                                                 const float* __restrict__ pnw,
                                                 const float* __restrict__ pnb) {
    int p = blockIdx.x;
    int tid = threadIdx.x;
    float* out = g_norm + (size_t)p * D_IN;
    int d0 = dom_of(p);
    bool pad = (p - g_off[d0]) >= g_cnt[d0];
    if (pad) {
        float4 z = {0.f, 0.f, 0.f, 0.f};
        *(float4*)&out[tid * 4] = z;
        return;
    }
    int r = g_perm[p];
    const float* xr = x + (size_t)r * D_IN;
    float4 v = *(const float4*)&xr[tid * 4];
    float s = v.x + v.y + v.z + v.w;
    float q = v.x * v.x + v.y * v.y + v.z * v.z + v.w * v.w;
    #pragma unroll
    for (int o = 16; o; o >>= 1) {
        s += __shfl_xor_sync(0xFFFFFFFFu, s, o);
        q += __shfl_xor_sync(0xFFFFFFFFu, q, o);
    }
    __shared__ float ss[8], sq[8];
    __shared__ float smean, sinv;
    if ((tid & 31) == 0) { ss[tid >> 5] = s; sq[tid >> 5] = q; }
    __syncthreads();
    if (tid < 32) {
        s = (tid < 8) ? ss[tid] : 0.f;
        q = (tid < 8) ? sq[tid] : 0.f;
        #pragma unroll
        for (int o = 4; o; o >>= 1) {
            s += __shfl_xor_sync(0xFFFFFFFFu, s, o);
            q += __shfl_xor_sync(0xFFFFFFFFu, q, o);
        }
        if (tid == 0) {
            float mean = s * (1.f / D_IN);
            float var = q * (1.f / D_IN) - mean * mean;
            smean = mean;
            sinv = rsqrtf(var + 1e-5f);
        }
    }
    __syncthreads();
    int d = dids[r];
    float4 w = *(const float4*)&pnw[(size_t)d * D_IN + tid * 4];
    float4 b = *(const float4*)&pnb[(size_t)d * D_IN + tid * 4];
    float m = smean, inv = sinv;
    float4 o;
    o.x = (v.x - m) * inv * w.x + b.x;
    o.y = (v.y - m) * inv * w.y + b.y;
    o.z = (v.z - m) * inv * w.z + b.z;
    o.w = (v.w - m) * inv * w.w + b.w;
    *(float4*)&out[tid * 4] = o;
}

// ---------------- tiled GEMM v2: 128x128x16, duplicated-A f32x2, double-buffered ----
// As stores each A value twice: As[kk][2m]=As[kk][2m+1]=A[m0+m][k0+kk], so one
// LDS.128 yields two ready f32x2 broadcast pairs (no pack MOVs).
// B tiles via cp.async; one __syncthreads per k-tile.
template <int K, int N, bool RELU, int LAYER>
__global__ __launch_bounds__(256, 2) void gemm_kernel(const float* __restrict__ Wc,
                                                      const float* __restrict__ Wd,
                                                      const float* __restrict__ bc,
                                                      const float* __restrict__ bd) {
    constexpr int BM = 128, BNT = 128, BK = 16;
    __shared__ float As[2][BK][2 * BM];   // duplicated: 2 x 16KB
    __shared__ float Bs[2][BK][BNT];      // 2 x 8KB

    const int tid = threadIdx.x;
    const int tx = tid & 15, ty = tid >> 4;
    const int by = blockIdx.y, bx = blockIdx.x;
    const int z = blockIdx.z;
    const int m0 = by * BM;
    const int n0 = bx * BNT;

    const float* A; float* C;
    if constexpr (LAYER == 1) { A = g_norm;               C = z ? g_h1d : g_h1c; }
    if constexpr (LAYER == 2) { A = z ? g_h1d : g_h1c;    C = z ? g_h2d : g_h2c; }
    if constexpr (LAYER == 3) { A = z ? g_h2d : g_h2c;    C = z ? g_h3d : g_h3c; }

    const float* W; const float* bias;
    if (z == 0) { W = Wc; bias = bc; }
    else {
        int dom = dom_of(m0);
        W = Wd + (size_t)dom * K * N;
        bias = bd + (size_t)dom * N;
    }

    // loader coords (2 16B chunks each for A and B per thread)
    const int ar0 = tid >> 2,          ac0 = (tid & 3) * 4;          // A chunk 0
    const int ar1 = (tid + 256) >> 2,  ac1 = (tid & 3) * 4;          // A chunk 1
    const int bk0 = tid >> 5,          bn0_ = (tid & 31) * 4;        // B chunk 0
    const int bk1 = (tid + 256) >> 5,  bn1_ = (tid & 31) * 4;        // B chunk 1
    const uint32_t sB = smem_u32(Bs);

    u64 acc[8][4];
    #pragma unroll
    for (int i = 0; i < 8; i++)
        #pragma unroll
        for (int j = 0; j < 4; j++) acc[i][j] = 0ull;

    constexpr int NT = K / BK;

    // prologue: tile 0
    float4 av0 = *(const float4*)&A[(size_t)(m0 + ar0) * K + ac0];
    float4 av1 = *(const float4*)&A[(size_t)(m0 + ar1) * K + ac1];
    cp_async16(sB + (bk0 * BNT + bn0_) * 4, &W[(size_t)bk0 * N + n0 + bn0_]);
    cp_async16(sB + (bk1 * BNT + bn1_) * 4, &W[(size_t)bk1 * N + n0 + bn1_]);
    cp_commit();
    {
        float2 d0 = {av0.x, av0.x}, d1 = {av0.y, av0.y};
        float2 d2 = {av0.z, av0.z}, d3 = {av0.w, av0.w};
        *(float2*)&As[0][ac0 + 0][2 * ar0] = d0;
        *(float2*)&As[0][ac0 + 1][2 * ar0] = d1;
        *(float2*)&As[0][ac0 + 2][2 * ar0] = d2;
        *(float2*)&As[0][ac0 + 3][2 * ar0] = d3;
        float2 e0 = {av1.x, av1.x}, e1 = {av1.y, av1.y};
        float2 e2 = {av1.z, av1.z}, e3 = {av1.w, av1.w};
        *(float2*)&As[0][ac1 + 0][2 * ar1] = e0;
        *(float2*)&As[0][ac1 + 1][2 * ar1] = e1;
        *(float2*)&As[0][ac1 + 2][2 * ar1] = e2;
        *(float2*)&As[0][ac1 + 3][2 * ar1] = e3;
    }

    for (int t = 0; t < NT; t++) {
        const int s = t & 1;
        const bool more = (t + 1) < NT;
        if (more) {
            const int k0 = (t + 1) * BK;
            av0 = *(const float4*)&A[(size_t)(m0 + ar0) * K + k0 + ac0];
            av1 = *(const float4*)&A[(size_t)(m0 + ar1) * K + k0 + ac1];
            uint32_t dstB = sB + (s ^ 1) * (BK * BNT * 4);
            cp_async16(dstB + (bk0 * BNT + bn0_) * 4, &W[(size_t)(k0 + bk0) * N + n0 + bn0_]);
            cp_async16(dstB + (bk1 * BNT + bn1_) * 4, &W[(size_t)(k0 + bk1) * N + n0 + bn1_]);
            cp_commit();
            cp_wait<1>();
        } else {
            cp_wait<0>();
        }
        __syncthreads();

        #pragma unroll
        for (int kk = 0; kk < BK; kk++) {
            u64 ap[8];
            *(uint4*)&ap[0] = *(const uint4*)&As[s][kk][8 * ty];
            *(uint4*)&ap[2] = *(const uint4*)&As[s][kk][8 * ty + 4];
            *(uint4*)&ap[4] = *(const uint4*)&As[s][kk][128 + 8 * ty];
            *(uint4*)&ap[6] = *(const uint4*)&As[s][kk][128 + 8 * ty + 4];
            const u64* bp0 = (const u64*)&Bs[s][kk][tx * 4];
            const u64* bp1 = (const u64*)&Bs[s][kk][tx * 4 + 64];
            u64 b0 = bp0[0], b1 = bp0[1], b2 = bp1[0], b3 = bp1[1];
            #pragma unroll
            for (int i = 0; i < 8; i++) {
                fma2(acc[i][0], ap[i], b0);
                fma2(acc[i][1], ap[i], b1);
                fma2(acc[i][2], ap[i], b2);
                fma2(acc[i][3], ap[i], b3);
            }
        }

        if (more) {
            const int sn = s ^ 1;
            float2 d0 = {av0.x, av0.x}, d1 = {av0.y, av0.y};
            float2 d2 = {av0.z, av0.z}, d3 = {av0.w, av0.w};
            *(float2*)&As[sn][ac0 + 0][2 * ar0] = d0;
            *(float2*)&As[sn][ac0 + 1][2 * ar0] = d1;
            *(float2*)&As[sn][ac0 + 2][2 * ar0] = d2;
            *(float2*)&As[sn][ac0 + 3][2 * ar0] = d3;
            float2 e0 = {av1.x, av1.x}, e1 = {av1.y, av1.y};
            float2 e2 = {av1.z, av1.z}, e3 = {av1.w, av1.w};
            *(float2*)&As[sn][ac1 + 0][2 * ar1] = e0;
            *(float2*)&As[sn][ac1 + 1][2 * ar1] = e1;
            *(float2*)&As[sn][ac1 + 2][2 * ar1] = e2;
            *(float2*)&As[sn][ac1 + 3][2 * ar1] = e3;
        }
    }

    float bj[8];
    #pragma unroll
    for (int j = 0; j < 8; j++) {
        int cn = tx * 4 + (j & 3) + ((j >> 2) * 64);
        bj[j] = bias[n0 + cn];
    }
    #pragma unroll
    for (int i = 0; i < 8; i++) {
        int m = m0 + ty * 4 + (i & 3) + ((i >> 2) * 64);
        float2 c0 = unpack2(acc[i][0]);
        float2 c1 = unpack2(acc[i][1]);
        float2 c2 = unpack2(acc[i][2]);
        float2 c3 = unpack2(acc[i][3]);
        float4 o0, o1;
        o0.x = c0.x + bj[0]; o0.y = c0.y + bj[1];
        o0.z = c1.x + bj[2]; o0.w = c1.y + bj[3];
        o1.x = c2.x + bj[4]; o1.y = c2.y + bj[5];
        o1.z = c3.x + bj[6]; o1.w = c3.y + bj[7];
        if (RELU) {
            o0.x = fmaxf(o0.x, 0.f); o0.y = fmaxf(o0.y, 0.f);
            o0.z = fmaxf(o0.z, 0.f); o0.w = fmaxf(o0.w, 0.f);
            o1.x = fmaxf(o1.x, 0.f); o1.y = fmaxf(o1.y, 0.f);
            o1.z = fmaxf(o1.z, 0.f); o1.w = fmaxf(o1.w, 0.f);
        }
        *(float4*)&C[(size_t)m * N + n0 + tx * 4]      = o0;
        *(float4*)&C[(size_t)m * N + n0 + tx * 4 + 64] = o1;
    }
}

// ---------------- fuse + final MLP + aux + sigmoid (one warp per row) ----------------
__global__ __launch_bounds__(256) void final_kernel(const float* __restrict__ fW1,
                                                    const float* __restrict__ fb1,
                                                    const float* __restrict__ fW2,
                                                    const float* __restrict__ fb2,
                                                    float* __restrict__ out) {
    __shared__ float sW1[H3 * FH];
    __shared__ float sb1[FH], sW2[FH];
    __shared__ float sf[8][H3];

    int tid = threadIdx.x;
    for (int i = tid; i < H3 * FH; i += 256) sW1[i] = fW1[i];
    if (tid < FH) { sb1[tid] = fb1[tid]; sW2[tid] = fW2[tid]; }
    __syncthreads();

    int w = tid >> 5, lane = tid & 31;
    int p = blockIdx.x * 8 + w;
    int d0 = dom_of(p);
    bool pad = (p - g_off[d0]) >= g_cnt[d0];

    #pragma unroll
    for (int q = 0; q < 4; q++) {
        int i = q * 32 + lane;
        float c = g_h3c[(size_t)p * H3 + i];
        float d = g_h3d[(size_t)p * H3 + i];
        sf[w][i] = c * tanhf(d);
    }
    __syncwarp();

    float acc = 0.f;
    #pragma unroll
    for (int jj = 0; jj < 2; jj++) {
        int j = jj * 32 + lane;
        float h = sb1[j];
        #pragma unroll 8
        for (int i = 0; i < H3; i++) h += sf[w][i] * sW1[i * FH + j];
        acc += fmaxf(h, 0.f) * sW2[j];
    }
    #pragma unroll
    for (int o = 16; o; o >>= 1) acc += __shfl_xor_sync(0xFFFFFFFFu, acc, o);

    if (lane == 0 && !pad) {
        int r = g_perm[p];
        float v = acc + fb2[0] + g_aux[d0];
        out[r] = 1.f / (1.f + expf(-v));
    }
}

// ---------------- launch ----------------
extern "C" void kernel_launch(void* const* d_in, const int* in_sizes, int n_in,
                              void* d_out, int out_size) {
    const float* x      = (const float*)d_in[0];
    const int*   dids   = (const int*)  d_in[1];
    const float* pnw    = (const float*)d_in[2];
    const float* pnb    = (const float*)d_in[3];
    const float* cW1    = (const float*)d_in[4];
    const float* cb1    = (const float*)d_in[5];
    const float* cW2    = (const float*)d_in[6];
    const float* cb2    = (const float*)d_in[7];
    const float* cW3    = (const float*)d_in[8];
    const float* cb3    = (const float*)d_in[9];
    const float* dW1    = (const float*)d_in[10];
    const float* db1    = (const float*)d_in[11];
    const float* dW2    = (const float*)d_in[12];
    const float* db2    = (const float*)d_in[13];
    const float* dW3    = (const float*)d_in[14];
    const float* db3    = (const float*)d_in[15];
    const float* fW1    = (const float*)d_in[16];
    const float* fb1    = (const float*)d_in[17];
    const float* fW2    = (const float*)d_in[18];
    const float* fb2    = (const float*)d_in[19];
    const float* dom_emb= (const float*)d_in[20];
    const float* aW1    = (const float*)d_in[21];
    const float* ab1    = (const float*)d_in[22];
    const float* aW2    = (const float*)d_in[23];
    const float* ab2    = (const float*)d_in[24];
    float* out = (float*)d_out;

    count_kernel<<<NCB, 256>>>(dids);                 // 0
    scatter_kernel<<<NCB, 256>>>(dids);               // 1
    ln_kernel<<<BP, 256>>>(x, dids, pnw, pnb);        // 2

    gemm_kernel<D_IN, H1, true,  1>                   // 3
        <<<dim3(H1 / 128, BP / 128, 2), 256>>>(cW1, dW1, cb1, db1);
    gemm_kernel<H1,   H2, true,  2>                   // 4
        <<<dim3(H2 / 128, BP / 128, 2), 256>>>(cW2, dW2, cb2, db2);
    gemm_kernel<H2,   H3, false, 3>                   // 5
        <<<dim3(H3 / 128, BP / 128, 2), 256>>>(cW3, dW3, cb3, db3);

    aux_kernel<<<1, 128>>>(dom_emb, aW1, ab1, aW2, ab2);    // 6
    final_kernel<<<BP / 8, 256>>>(fW1, fb1, fW2, fb2, out); // 7
}

// round 8
// speedup vs baseline: 1.2862x; 1.2862x over previous
#include <cuda_runtime.h>
#include <math.h>
#include <cstdint>

// ---------------- problem constants ----------------
#define BN_ 16384
#define D_IN 1024
#define H1 512
#define H2 256
#define H3 128
#define FH 64
#define NDOM 4
#define EMB 16
#define BMROWS 128
#define BP 16896            // 132 tiles of 128 (>= 16384 + max padding 508)
#define NCB 64              // count blocks

// ---------------- scratch (device globals) ----------------
__device__ float g_norm[(size_t)BP * D_IN];
__device__ float g_h1c[(size_t)BP * H1];
__device__ float g_h1d[(size_t)BP * H1];
__device__ float g_h2c[(size_t)BP * H2];
__device__ float g_h2d[(size_t)BP * H2];
__device__ float g_h3c[(size_t)BP * H3];
__device__ float g_h3d[(size_t)BP * H3];
__device__ int   g_perm[BP];
__device__ int   g_bcnt[NCB][NDOM];
__device__ int   g_cnt[NDOM];
__device__ int   g_off[NDOM];
__device__ float g_aux[NDOM];

typedef unsigned long long u64;

// ---------------- f32x2 helpers ----------------
__device__ __forceinline__ u64 pack2(float x) {
    u64 r;
    asm("mov.b64 %0, {%1, %1};" : "=l"(r) : "r"(__float_as_uint(x)));
    return r;
}
__device__ __forceinline__ void fma2(u64& d, u64 a, u64 b) {
    asm("fma.rn.f32x2 %0, %1, %2, %0;" : "+l"(d) : "l"(a), "l"(b));
}
__device__ __forceinline__ float2 unpack2(u64 v) {
    uint32_t lo, hi;
    asm("mov.b64 {%0, %1}, %2;" : "=r"(lo), "=r"(hi) : "l"(v));
    float2 f;
    f.x = __uint_as_float(lo);
    f.y = __uint_as_float(hi);
    return f;
}

__device__ __forceinline__ uint32_t smem_u32(const void* p) {
    uint32_t a;
    asm("{ .reg .u64 t; cvta.to.shared.u64 t, %1; cvt.u32.u64 %0, t; }" : "=r"(a) : "l"(p));
    return a;
}
__device__ __forceinline__ void cp_async16(uint32_t dst, const void* src) {
    asm volatile("cp.async.ca.shared.global [%0], [%1], 16;"
                 :: "r"(dst), "l"(src) : "memory");
}
__device__ __forceinline__ void cp_commit() {
    asm volatile("cp.async.commit_group;" ::: "memory");
}
template <int N>
__device__ __forceinline__ void cp_wait() {
    asm volatile("cp.async.wait_group %0;" :: "n"(N) : "memory");
}

// pad region helpers
__device__ __forceinline__ int pad4(int c) { return (c + BMROWS - 1) & ~(BMROWS - 1); }

__device__ __forceinline__ int dom_of(int p) {
    int d = 0;
    #pragma unroll
    for (int k = 1; k < NDOM; k++) d += (p >= g_off[k]);
    return d;
}

// ---------------- sort: count (per-block partials) ----------------
__global__ __launch_bounds__(256) void count_kernel(const int* __restrict__ dids) {
    __shared__ int sc[NDOM];
    int tid = threadIdx.x;
    if (tid < NDOM) sc[tid] = 0;
    __syncthreads();
    int i = blockIdx.x * 256 + tid;
    atomicAdd(&sc[dids[i]], 1);
    __syncthreads();
    if (tid < NDOM) g_bcnt[blockIdx.x][tid] = sc[tid];
}

// ---------------- sort: scatter with inline prefix (publishes off/cnt) ----------------
__global__ __launch_bounds__(256) void scatter_kernel(const int* __restrict__ dids) {
    __shared__ int pre[NDOM];
    __shared__ int loc[NDOM];
    __shared__ int stot[NDOM], sbase[NDOM];
    int tid = threadIdx.x;
    if (tid < NDOM) {
        int d = tid, base = 0, tot = 0;
        #pragma unroll 8
        for (int b = 0; b < NCB; b++) {
            int c = g_bcnt[b][d];
            if (b < (int)blockIdx.x) base += c;
            tot += c;
        }
        stot[d] = tot; sbase[d] = base;
        loc[d] = 0;
    }
    __syncthreads();
    if (tid == 0) {
        int off = 0;
        #pragma unroll
        for (int d = 0; d < NDOM; d++) {
            pre[d] = off + sbase[d];
            if (blockIdx.x == 0) { g_off[d] = off; g_cnt[d] = stot[d]; }
            off += pad4(stot[d]);
        }
    }
    __syncthreads();
    int i = blockIdx.x * 256 + tid;
    int d = dids[i];
    int rank = atomicAdd(&loc[d], 1);
    g_perm[pre[d] + rank] = i;
}

// aux net (domain-only) -> 4 scalars
__global__ void aux_kernel(const float* __restrict__ dom_emb,
                           const float* __restrict__ aW1, const float* __restrict__ ab1,
                           const float* __restrict__ aW2, const float* __restrict__ ab2) {
    int w = threadIdx.x >> 5;
    int j = threadIdx.x & 31;
    float s = ab1[j];
    #pragma unroll
    for (int i = 0; i < EMB; i++) s += dom_emb[w * EMB + i] * aW1[i * 32 + j];
    float v = fmaxf(s, 0.f) * aW2[j];
    #pragma unroll
    for (int o = 16; o; o >>= 1) v += __shfl_xor_sync(0xFFFFFFFFu, v, o);
    if (j == 0) g_aux[w] = v + ab2[0];
}

// ---------------- layernorm + domain affine, permuted order ----------------
__global__ __launch_bounds__(256) void ln_kernel(const float* __restrict__ x,
                                                 const int* __restrict__ dids,
                                                 const float* __restrict__ pnw,
                                                 const float* __restrict__ pnb) {
    int p = blockIdx.x;
    int tid = threadIdx.x;
    float* out = g_norm + (size_t)p * D_IN;
    int d0 = dom_of(p);
    bool pad = (p - g_off[d0]) >= g_cnt[d0];
    if (pad) {
        float4 z = {0.f, 0.f, 0.f, 0.f};
        *(float4*)&out[tid * 4] = z;
        return;
    }
    int r = g_perm[p];
    const float* xr = x + (size_t)r * D_IN;
    float4 v = *(const float4*)&xr[tid * 4];
    float s = v.x + v.y + v.z + v.w;
    float q = v.x * v.x + v.y * v.y + v.z * v.z + v.w * v.w;
    #pragma unroll
    for (int o = 16; o; o >>= 1) {
        s += __shfl_xor_sync(0xFFFFFFFFu, s, o);
        q += __shfl_xor_sync(0xFFFFFFFFu, q, o);
    }
    __shared__ float ss[8], sq[8];
    __shared__ float smean, sinv;
    if ((tid & 31) == 0) { ss[tid >> 5] = s; sq[tid >> 5] = q; }
    __syncthreads();
    if (tid < 32) {
        s = (tid < 8) ? ss[tid] : 0.f;
        q = (tid < 8) ? sq[tid] : 0.f;
        #pragma unroll
        for (int o = 4; o; o >>= 1) {
            s += __shfl_xor_sync(0xFFFFFFFFu, s, o);
            q += __shfl_xor_sync(0xFFFFFFFFu, q, o);
        }
        if (tid == 0) {
            float mean = s * (1.f / D_IN);
            float var = q * (1.f / D_IN) - mean * mean;
            smean = mean;
            sinv = rsqrtf(var + 1e-5f);
        }
    }
    __syncthreads();
    int d = dids[r];
    float4 w = *(const float4*)&pnw[(size_t)d * D_IN + tid * 4];
    float4 b = *(const float4*)&pnb[(size_t)d * D_IN + tid * 4];
    float m = smean, inv = sinv;
    float4 o;
    o.x = (v.x - m) * inv * w.x + b.x;
    o.y = (v.y - m) * inv * w.y + b.y;
    o.z = (v.z - m) * inv * w.z + b.z;
    o.w = (v.w - m) * inv * w.w + b.w;
    *(float4*)&out[tid * 4] = o;
}

// ---------------- tiled GEMM v3: R4 layout + double buffering ----------------
// As[stage][BK][BM] transposed (R4-proven, conflict-free), Bs via cp.async ring.
// A for tile t+1 is LDG'd before compute of tile t and STS'd after compute.
// Exactly one __syncthreads per k-tile.
template <int K, int N, bool RELU, int LAYER>
__global__ __launch_bounds__(256, 2) void gemm_kernel(const float* __restrict__ Wc,
                                                      const float* __restrict__ Wd,
                                                      const float* __restrict__ bc,
                                                      const float* __restrict__ bd) {
    constexpr int BM = 128, BNT = 128, BK = 16;
    __shared__ float As[2][BK][BM];    // 2 x 8KB
    __shared__ float Bs[2][BK][BNT];   // 2 x 8KB

    const int tid = threadIdx.x;
    const int tx = tid & 15, ty = tid >> 4;
    const int by = blockIdx.y, bx = blockIdx.x;
    const int z = blockIdx.z;
    const int m0 = by * BM;
    const int n0 = bx * BNT;

    const float* A; float* C;
    if constexpr (LAYER == 1) { A = g_norm;               C = z ? g_h1d : g_h1c; }
    if constexpr (LAYER == 2) { A = z ? g_h1d : g_h1c;    C = z ? g_h2d : g_h2c; }
    if constexpr (LAYER == 3) { A = z ? g_h2d : g_h2c;    C = z ? g_h3d : g_h3c; }

    const float* W; const float* bias;
    if (z == 0) { W = Wc; bias = bc; }
    else {
        int dom = dom_of(m0);
        W = Wd + (size_t)dom * K * N;
        bias = bd + (size_t)dom * N;
    }

    // loader coords
    const int ar0 = tid >> 2,          ac0 = (tid & 3) * 4;   // A rows 0..63
    const int ar1 = (tid + 256) >> 2;                          // A rows 64..127
    const int bk0 = tid >> 5,          bn0_ = (tid & 31) * 4;  // B k 0..7
    const int bk1 = (tid + 256) >> 5;                          // B k 8..15
    const uint32_t sB = smem_u32(Bs);

    u64 acc[8][4];
    #pragma unroll
    for (int i = 0; i < 8; i++)
        #pragma unroll
        for (int j = 0; j < 4; j++) acc[i][j] = 0ull;

    constexpr int NT = K / BK;

    // prologue: tile 0
    float4 av0 = *(const float4*)&A[(size_t)(m0 + ar0) * K + ac0];
    float4 av1 = *(const float4*)&A[(size_t)(m0 + ar1) * K + ac0];
    cp_async16(sB + (bk0 * BNT + bn0_) * 4, &W[(size_t)bk0 * N + n0 + bn0_]);
    cp_async16(sB + (bk1 * BNT + bn0_) * 4, &W[(size_t)bk1 * N + n0 + bn0_]);
    cp_commit();
    As[0][ac0 + 0][ar0] = av0.x;
    As[0][ac0 + 1][ar0] = av0.y;
    As[0][ac0 + 2][ar0] = av0.z;
    As[0][ac0 + 3][ar0] = av0.w;
    As[0][ac0 + 0][ar1] = av1.x;
    As[0][ac0 + 1][ar1] = av1.y;
    As[0][ac0 + 2][ar1] = av1.z;
    As[0][ac0 + 3][ar1] = av1.w;

    for (int t = 0; t < NT; t++) {
        const int s = t & 1;
        const bool more = (t + 1) < NT;
        if (more) {
            const int k0 = (t + 1) * BK;
            av0 = *(const float4*)&A[(size_t)(m0 + ar0) * K + k0 + ac0];
            av1 = *(const float4*)&A[(size_t)(m0 + ar1) * K + k0 + ac0];
            uint32_t dstB = sB + (s ^ 1) * (BK * BNT * 4);
            cp_async16(dstB + (bk0 * BNT + bn0_) * 4, &W[(size_t)(k0 + bk0) * N + n0 + bn0_]);
            cp_async16(dstB + (bk1 * BNT + bn0_) * 4, &W[(size_t)(k0 + bk1) * N + n0 + bn0_]);
            cp_commit();
            cp_wait<1>();
        } else {
            cp_wait<0>();
        }
        __syncthreads();

        #pragma unroll
        for (int kk = 0; kk < BK; kk++) {
            float a[8];
            *(float4*)&a[0] = *(const float4*)&As[s][kk][ty * 4];
            *(float4*)&a[4] = *(const float4*)&As[s][kk][ty * 4 + 64];
            const u64* bp0 = (const u64*)&Bs[s][kk][tx * 4];
            const u64* bp1 = (const u64*)&Bs[s][kk][tx * 4 + 64];
            u64 b0 = bp0[0], b1 = bp0[1], b2 = bp1[0], b3 = bp1[1];
            #pragma unroll
            for (int i = 0; i < 8; i++) {
                u64 ai = pack2(a[i]);
                fma2(acc[i][0], ai, b0);
                fma2(acc[i][1], ai, b1);
                fma2(acc[i][2], ai, b2);
                fma2(acc[i][3], ai, b3);
            }
        }

        if (more) {
            const int sn = s ^ 1;
            As[sn][ac0 + 0][ar0] = av0.x;
            As[sn][ac0 + 1][ar0] = av0.y;
            As[sn][ac0 + 2][ar0] = av0.z;
            As[sn][ac0 + 3][ar0] = av0.w;
            As[sn][ac0 + 0][ar1] = av1.x;
            As[sn][ac0 + 1][ar1] = av1.y;
            As[sn][ac0 + 2][ar1] = av1.z;
            As[sn][ac0 + 3][ar1] = av1.w;
        }
    }

    float bj[8];
    #pragma unroll
    for (int j = 0; j < 8; j++) {
        int cn = tx * 4 + (j & 3) + ((j >> 2) * 64);
        bj[j] = bias[n0 + cn];
    }
    #pragma unroll
    for (int i = 0; i < 8; i++) {
        int m = m0 + ty * 4 + (i & 3) + ((i >> 2) * 64);
        float2 c0 = unpack2(acc[i][0]);
        float2 c1 = unpack2(acc[i][1]);
        float2 c2 = unpack2(acc[i][2]);
        float2 c3 = unpack2(acc[i][3]);
        float4 o0, o1;
        o0.x = c0.x + bj[0]; o0.y = c0.y + bj[1];
        o0.z = c1.x + bj[2]; o0.w = c1.y + bj[3];
        o1.x = c2.x + bj[4]; o1.y = c2.y + bj[5];
        o1.z = c3.x + bj[6]; o1.w = c3.y + bj[7];
        if (RELU) {
            o0.x = fmaxf(o0.x, 0.f); o0.y = fmaxf(o0.y, 0.f);
            o0.z = fmaxf(o0.z, 0.f); o0.w = fmaxf(o0.w, 0.f);
            o1.x = fmaxf(o1.x, 0.f); o1.y = fmaxf(o1.y, 0.f);
            o1.z = fmaxf(o1.z, 0.f); o1.w = fmaxf(o1.w, 0.f);
        }
        *(float4*)&C[(size_t)m * N + n0 + tx * 4]      = o0;
        *(float4*)&C[(size_t)m * N + n0 + tx * 4 + 64] = o1;
    }
}

// ---------------- fuse + final MLP + aux + sigmoid (one warp per row) ----------------
__global__ __launch_bounds__(256) void final_kernel(const float* __restrict__ fW1,
                                                    const float* __restrict__ fb1,
                                                    const float* __restrict__ fW2,
                                                    const float* __restrict__ fb2,
                                                    float* __restrict__ out) {
    __shared__ float sW1[H3 * FH];
    __shared__ float sb1[FH], sW2[FH];
    __shared__ float sf[8][H3];

    int tid = threadIdx.x;
    for (int i = tid; i < H3 * FH; i += 256) sW1[i] = fW1[i];
    if (tid < FH) { sb1[tid] = fb1[tid]; sW2[tid] = fW2[tid]; }
    __syncthreads();

    int w = tid >> 5, lane = tid & 31;
    int p = blockIdx.x * 8 + w;
    int d0 = dom_of(p);
    bool pad = (p - g_off[d0]) >= g_cnt[d0];

    #pragma unroll
    for (int q = 0; q < 4; q++) {
        int i = q * 32 + lane;
        float c = g_h3c[(size_t)p * H3 + i];
        float d = g_h3d[(size_t)p * H3 + i];
        sf[w][i] = c * tanhf(d);
    }
    __syncwarp();

    float acc = 0.f;
    #pragma unroll
    for (int jj = 0; jj < 2; jj++) {
        int j = jj * 32 + lane;
        float h = sb1[j];
        #pragma unroll 8
        for (int i = 0; i < H3; i++) h += sf[w][i] * sW1[i * FH + j];
        acc += fmaxf(h, 0.f) * sW2[j];
    }
    #pragma unroll
    for (int o = 16; o; o >>= 1) acc += __shfl_xor_sync(0xFFFFFFFFu, acc, o);

    if (lane == 0 && !pad) {
        int r = g_perm[p];
        float v = acc + fb2[0] + g_aux[d0];
        out[r] = 1.f / (1.f + expf(-v));
    }
}

// ---------------- launch ----------------
extern "C" void kernel_launch(void* const* d_in, const int* in_sizes, int n_in,
                              void* d_out, int out_size) {
    const float* x      = (const float*)d_in[0];
    const int*   dids   = (const int*)  d_in[1];
    const float* pnw    = (const float*)d_in[2];
    const float* pnb    = (const float*)d_in[3];
    const float* cW1    = (const float*)d_in[4];
    const float* cb1    = (const float*)d_in[5];
    const float* cW2    = (const float*)d_in[6];
    const float* cb2    = (const float*)d_in[7];
    const float* cW3    = (const float*)d_in[8];
    const float* cb3    = (const float*)d_in[9];
    const float* dW1    = (const float*)d_in[10];
    const float* db1    = (const float*)d_in[11];
    const float* dW2    = (const float*)d_in[12];
    const float* db2    = (const float*)d_in[13];
    const float* dW3    = (const float*)d_in[14];
    const float* db3    = (const float*)d_in[15];
    const float* fW1    = (const float*)d_in[16];
    const float* fb1    = (const float*)d_in[17];
    const float* fW2    = (const float*)d_in[18];
    const float* fb2    = (const float*)d_in[19];
    const float* dom_emb= (const float*)d_in[20];
    const float* aW1    = (const float*)d_in[21];
    const float* ab1    = (const float*)d_in[22];
    const float* aW2    = (const float*)d_in[23];
    const float* ab2    = (const float*)d_in[24];
    float* out = (float*)d_out;

    count_kernel<<<NCB, 256>>>(dids);                 // 0
    scatter_kernel<<<NCB, 256>>>(dids);               // 1
    ln_kernel<<<BP, 256>>>(x, dids, pnw, pnb);        // 2

    gemm_kernel<D_IN, H1, true,  1>                   // 3
        <<<dim3(H1 / 128, BP / 128, 2), 256>>>(cW1, dW1, cb1, db1);
    gemm_kernel<H1,   H2, true,  2>                   // 4
        <<<dim3(H2 / 128, BP / 128, 2), 256>>>(cW2, dW2, cb2, db2);
    gemm_kernel<H2,   H3, false, 3>                   // 5
        <<<dim3(H3 / 128, BP / 128, 2), 256>>>(cW3, dW3, cb3, db3);

    aux_kernel<<<1, 128>>>(dom_emb, aW1, ab1, aW2, ab2);    // 6
    final_kernel<<<BP / 8, 256>>>(fW1, fb1, fW2, fb2, out); // 7
}